// round 1
// baseline (speedup 1.0000x reference)
#include <cuda_runtime.h>

#define D 128
#define NMAX 50000

// scratch: aggregated messages per node (allocation-free: device global)
__device__ float g_agg[(size_t)NMAX * D];

// ---------------------------------------------------------------------------
// Edge kernel: one warp per edge. msg = h[dst] * e_h, scatter-add into agg.
// Each lane handles 4 consecutive floats (float4 loads, 4 scalar red.add).
// ---------------------------------------------------------------------------
__global__ void edge_kernel(const float* __restrict__ h,
                            const float* __restrict__ e_h,
                            const int* __restrict__ dst,
                            float* __restrict__ agg,
                            int E) {
    int gw   = (blockIdx.x * blockDim.x + threadIdx.x) >> 5;
    int lane = threadIdx.x & 31;
    if (gw >= E) return;

    int d = __ldg(dst + gw);
    float4 hv = ((const float4*)(h   + (size_t)d  * D))[lane];
    float4 ev = ((const float4*)(e_h + (size_t)gw * D))[lane];

    float* o = agg + (size_t)d * D + lane * 4;
    atomicAdd(o + 0, hv.x * ev.x);
    atomicAdd(o + 1, hv.y * ev.y);
    atomicAdd(o + 2, hv.z * ev.z);
    atomicAdd(o + 3, hv.w * ev.w);
}

// ---------------------------------------------------------------------------
// GEMM kernel: out[n][j] = (sum_k agg[n][k] * W[j][k] + b[j]) * norm[n]
// Classic shared-tiled SGEMM: block tile 128 nodes x 128 cols, K chunked by 32,
// 256 threads, 8x8 register tile per thread.
// ---------------------------------------------------------------------------
__global__ void gemm_kernel(const float* __restrict__ agg,
                            const float* __restrict__ W,
                            const float* __restrict__ b,
                            const float* __restrict__ norm,
                            float* __restrict__ out,
                            int N) {
    __shared__ float As[128][33];   // [node][k]  (padded)
    __shared__ float Ws[32][129];   // [k][col]   (padded, W transposed)

    const int tx = threadIdx.x % 16;  // col group
    const int ty = threadIdx.x / 16;  // row group
    const int rowBase = blockIdx.x * 128;

    float acc[8][8];
    #pragma unroll
    for (int i = 0; i < 8; i++)
        #pragma unroll
        for (int j = 0; j < 8; j++) acc[i][j] = 0.0f;

    for (int kk = 0; kk < D; kk += 32) {
        // Load A tile: 128 rows x 32 k-cols (8 float4 per row, 1024 float4 total)
        for (int i = threadIdx.x; i < 128 * 8; i += 256) {
            int r  = i >> 3;
            int c4 = i & 7;
            int grow = rowBase + r;
            float4 v = make_float4(0.f, 0.f, 0.f, 0.f);
            if (grow < N)
                v = ((const float4*)(agg + (size_t)grow * D + kk))[c4];
            As[r][c4 * 4 + 0] = v.x;
            As[r][c4 * 4 + 1] = v.y;
            As[r][c4 * 4 + 2] = v.z;
            As[r][c4 * 4 + 3] = v.w;
        }
        // Load W tile transposed: Ws[k][j] = W[j][kk + k]
        for (int i = threadIdx.x; i < 128 * 8; i += 256) {
            int j  = i >> 3;
            int c4 = i & 7;
            float4 v = ((const float4*)(W + (size_t)j * D + kk))[c4];
            Ws[c4 * 4 + 0][j] = v.x;
            Ws[c4 * 4 + 1][j] = v.y;
            Ws[c4 * 4 + 2][j] = v.z;
            Ws[c4 * 4 + 3][j] = v.w;
        }
        __syncthreads();

        #pragma unroll
        for (int k = 0; k < 32; k++) {
            float a[8], w[8];
            #pragma unroll
            for (int i = 0; i < 8; i++) a[i] = As[ty * 8 + i][k];
            #pragma unroll
            for (int j = 0; j < 8; j++) w[j] = Ws[k][tx * 8 + j];
            #pragma unroll
            for (int i = 0; i < 8; i++)
                #pragma unroll
                for (int j = 0; j < 8; j++)
                    acc[i][j] = fmaf(a[i], w[j], acc[i][j]);
        }
        __syncthreads();
    }

    // Epilogue: add bias, scale by norm, write out
    #pragma unroll
    for (int i = 0; i < 8; i++) {
        int n = rowBase + ty * 8 + i;
        if (n >= N) continue;
        float nm = norm[n];
        #pragma unroll
        for (int j = 0; j < 8; j++) {
            int col = tx * 8 + j;
            out[(size_t)n * D + col] = (acc[i][j] + b[col]) * nm;
        }
    }
}

extern "C" void kernel_launch(void* const* d_in, const int* in_sizes, int n_in,
                              void* d_out, int out_size) {
    const float* h    = (const float*)d_in[0];
    const float* e_h  = (const float*)d_in[1];
    const float* norm = (const float*)d_in[2];
    const int*   dst  = (const int*)d_in[3];
    const float* W    = (const float*)d_in[4];
    const float* b    = (const float*)d_in[5];
    float*       out  = (float*)d_out;

    const int N = in_sizes[2];   // norm has N elements
    const int E = in_sizes[3];   // dst has E elements

    float* agg = nullptr;
    cudaGetSymbolAddress((void**)&agg, g_agg);

    // zero the aggregation buffer (graph-capturable memset node)
    cudaMemsetAsync(agg, 0, (size_t)N * D * sizeof(float), 0);

    // one warp per edge
    {
        int threads = 256;
        int warpsPerBlock = threads / 32;
        int blocks = (E + warpsPerBlock - 1) / warpsPerBlock;
        edge_kernel<<<blocks, threads>>>(h, e_h, dst, agg, E);
    }

    // tiled GEMM + epilogue
    {
        int blocks = (N + 127) / 128;
        gemm_kernel<<<blocks, 256>>>(agg, W, b, norm, out, N);
    }
}

// round 2
// speedup vs baseline: 1.7979x; 1.7979x over previous
#include <cuda_runtime.h>

#define D 128
#define NMAX 50000

// scratch: aggregated messages per node (allocation-free: device global)
__device__ float g_agg[(size_t)NMAX * D];

// ---------------------------------------------------------------------------
// Edge kernel: one warp per edge. msg = h[dst] * e_h, scatter-add into agg
// with a single vector atomic (red.global.add.v4.f32) per lane.
// ---------------------------------------------------------------------------
__global__ void edge_kernel(const float* __restrict__ h,
                            const float* __restrict__ e_h,
                            const int* __restrict__ dst,
                            float* __restrict__ agg,
                            int E) {
    int gw   = (blockIdx.x * blockDim.x + threadIdx.x) >> 5;
    int lane = threadIdx.x & 31;
    if (gw >= E) return;

    int d = __ldg(dst + gw);
    float4 hv = ((const float4*)(h   + (size_t)d  * D))[lane];
    float4 ev = ((const float4*)(e_h + (size_t)gw * D))[lane];

    float mx = hv.x * ev.x;
    float my = hv.y * ev.y;
    float mz = hv.z * ev.z;
    float mw = hv.w * ev.w;

    float* o = agg + (size_t)d * D + lane * 4;
    asm volatile("red.global.add.v4.f32 [%0], {%1, %2, %3, %4};"
                 :: "l"(o), "f"(mx), "f"(my), "f"(mz), "f"(mw)
                 : "memory");
}

// ---------------------------------------------------------------------------
// GEMM kernel: out[n][j] = (sum_k agg[n][k] * W[j][k] + b[j]) * norm[n]
// 128x128 block tile, 256 threads, 8x8 per thread as 2x2 float4 quadrants.
// Both smem tiles stored k-major for conflict-free LDS.128 in the mainloop.
// ---------------------------------------------------------------------------
#define KC 32
#define APAD 132   // 33 float4s per k-row; 528B row, 16B aligned

__global__ void __launch_bounds__(256)
gemm_kernel(const float* __restrict__ agg,
            const float* __restrict__ W,
            const float* __restrict__ b,
            const float* __restrict__ norm,
            float* __restrict__ out,
            int N) {
    __shared__ float As[KC][APAD];   // [k][row]
    __shared__ float Ws[KC][APAD];   // [k][col]  (Ws[k][j] = W[j][k])

    const int tid = threadIdx.x;
    const int tx = tid & 15;          // col group
    const int ty = tid >> 4;          // row group
    const int rowBase = blockIdx.x * 128;

    float acc[8][8];
    #pragma unroll
    for (int i = 0; i < 8; i++)
        #pragma unroll
        for (int j = 0; j < 8; j++) acc[i][j] = 0.0f;

    for (int kk = 0; kk < D; kk += KC) {
        // Load A tile transposed: As[k][row] = agg[rowBase+row][kk+k]
        // 128 rows x 32 k = 1024 float4 global loads, 4 per thread
        #pragma unroll
        for (int t = 0; t < 4; t++) {
            int i  = tid + t * 256;
            int r  = i >> 3;          // row 0..127
            int c4 = i & 7;           // k-float4 0..7
            int grow = rowBase + r;
            float4 v = make_float4(0.f, 0.f, 0.f, 0.f);
            if (grow < N)
                v = ((const float4*)(agg + (size_t)grow * D + kk))[c4];
            As[c4 * 4 + 0][r] = v.x;
            As[c4 * 4 + 1][r] = v.y;
            As[c4 * 4 + 2][r] = v.z;
            As[c4 * 4 + 3][r] = v.w;
        }
        // Load W tile: Ws[k][j] = W[j][kk+k]
        #pragma unroll
        for (int t = 0; t < 4; t++) {
            int i  = tid + t * 256;
            int j  = i >> 3;
            int c4 = i & 7;
            float4 v = ((const float4*)(W + (size_t)j * D + kk))[c4];
            Ws[c4 * 4 + 0][j] = v.x;
            Ws[c4 * 4 + 1][j] = v.y;
            Ws[c4 * 4 + 2][j] = v.z;
            Ws[c4 * 4 + 3][j] = v.w;
        }
        __syncthreads();

        #pragma unroll
        for (int k = 0; k < KC; k++) {
            float4 a0 = *(const float4*)&As[k][ty * 4];
            float4 a1 = *(const float4*)&As[k][ty * 4 + 64];
            float4 w0 = *(const float4*)&Ws[k][tx * 4];
            float4 w1 = *(const float4*)&Ws[k][tx * 4 + 64];
            float a[8] = {a0.x, a0.y, a0.z, a0.w, a1.x, a1.y, a1.z, a1.w};
            float w[8] = {w0.x, w0.y, w0.z, w0.w, w1.x, w1.y, w1.z, w1.w};
            #pragma unroll
            for (int i = 0; i < 8; i++)
                #pragma unroll
                for (int j = 0; j < 8; j++)
                    acc[i][j] = fmaf(a[i], w[j], acc[i][j]);
        }
        __syncthreads();
    }

    // Epilogue: add bias, scale by norm, vectorized stores.
    // Thread owns rows {ty*4+i, ty*4+64+i} x cols {tx*4+j, tx*4+64+j}
    #pragma unroll
    for (int iq = 0; iq < 2; iq++) {
        #pragma unroll
        for (int i = 0; i < 4; i++) {
            int n = rowBase + ty * 4 + iq * 64 + i;
            if (n >= N) continue;
            float nm = __ldg(norm + n);
            #pragma unroll
            for (int jq = 0; jq < 2; jq++) {
                int col = tx * 4 + jq * 64;
                float4 bb = *(const float4*)(b + col);
                float4 r;
                r.x = (acc[iq * 4 + i][jq * 4 + 0] + bb.x) * nm;
                r.y = (acc[iq * 4 + i][jq * 4 + 1] + bb.y) * nm;
                r.z = (acc[iq * 4 + i][jq * 4 + 2] + bb.z) * nm;
                r.w = (acc[iq * 4 + i][jq * 4 + 3] + bb.w) * nm;
                *(float4*)(out + (size_t)n * D + col) = r;
            }
        }
    }
}

extern "C" void kernel_launch(void* const* d_in, const int* in_sizes, int n_in,
                              void* d_out, int out_size) {
    const float* h    = (const float*)d_in[0];
    const float* e_h  = (const float*)d_in[1];
    const float* norm = (const float*)d_in[2];
    const int*   dst  = (const int*)d_in[3];
    const float* W    = (const float*)d_in[4];
    const float* b    = (const float*)d_in[5];
    float*       out  = (float*)d_out;

    const int N = in_sizes[2];   // norm has N elements
    const int E = in_sizes[3];   // dst has E elements

    float* agg = nullptr;
    cudaGetSymbolAddress((void**)&agg, g_agg);

    // zero the aggregation buffer (graph-capturable memset node)
    cudaMemsetAsync(agg, 0, (size_t)N * D * sizeof(float), 0);

    // one warp per edge
    {
        int threads = 256;
        int warpsPerBlock = threads / 32;
        int blocks = (E + warpsPerBlock - 1) / warpsPerBlock;
        edge_kernel<<<blocks, threads>>>(h, e_h, dst, agg, E);
    }

    // tiled GEMM + epilogue
    {
        int blocks = (N + 127) / 128;
        gemm_kernel<<<blocks, 256>>>(agg, W, b, norm, out, N);
    }
}